// round 8
// baseline (speedup 1.0000x reference)
#include <cuda_runtime.h>
#include <cuda_bf16.h>
#include <cstdint>

// Problem constants
#define NN      500000
#define DIM     256
#define JDIM    64
#define BMAX    512
#define SPLIT   8

// ---------------- device scratch (static, no allocation) ----------------
__device__ float    g_expw[NN];
__device__ int      g_segstart[BMAX + 1];
__device__ float    g_segsum[BMAX];
__device__ float    g_pooled[BMAX * DIM];
__device__ float    g_Wp[JDIM * DIM];   // W_att permuted into mma B-fragment order (tf32-rounded)
__device__ int      g_is64;

// ---------------- helpers ----------------
__device__ __forceinline__ uint32_t f2tf32(float f) {
    uint32_t u; asm("cvt.rna.tf32.f32 %0, %1;" : "=r"(u) : "f"(f)); return u;
}
__device__ __forceinline__ float tanh_apx(float x) {
    float y; asm("tanh.approx.f32 %0, %1;" : "=f"(y) : "f"(x)); return y;
}
__device__ __forceinline__ void mma_tf32(float (&c)[4],
        uint32_t a0, uint32_t a1, uint32_t a2, uint32_t a3,
        uint32_t b0, uint32_t b1) {
    asm volatile(
        "mma.sync.aligned.m16n8k8.row.col.f32.tf32.tf32.f32 "
        "{%0,%1,%2,%3}, {%4,%5,%6,%7}, {%8,%9}, {%0,%1,%2,%3};\n"
        : "+f"(c[0]), "+f"(c[1]), "+f"(c[2]), "+f"(c[3])
        : "r"(a0), "r"(a1), "r"(a2), "r"(a3), "r"(b0), "r"(b1));
}

// ---------------- kernel 0: detect batch dtype (int32 vs int64) ----------------
__global__ void detect_kernel(const void* batch) {
    const int* w = (const int*)batch;
    __shared__ int cnt;
    if (threadIdx.x == 0) cnt = 0;
    __syncthreads();
    int widx = 2 * 977 * (int)threadIdx.x + 1;   // odd 32-bit words, spread across array
    int z = (w[widx] == 0) ? 1 : 0;
    atomicAdd(&cnt, z);
    __syncthreads();
    if (threadIdx.x == 0) g_is64 = (cnt > 128) ? 1 : 0;
}

// ---------------- kernel 1: init scratch + build permuted W (tf32-rounded) ----------------
// Wp float index = (((ss*2+sub)*8 + t)*32 + lane)*2 + c
//   j = 8*t + lane/4 ; k = 16*ss + 4*(lane%4) + 2*sub + c
__global__ void init_kernel(const float* __restrict__ W_att) {
    int i = blockIdx.x * blockDim.x + threadIdx.x;
    if (i < BMAX * DIM) g_pooled[i] = 0.f;
    if (i < BMAX) g_segsum[i] = 0.f;
    if (i < JDIM * DIM) {
        int c    = i & 1;
        int lane = (i >> 1) & 31;
        int t    = (i >> 6) & 7;
        int sub  = (i >> 9) & 1;
        int ss   = i >> 10;
        int j = 8 * t + (lane >> 2);
        int k = 16 * ss + 4 * (lane & 3) + 2 * sub + c;
        float v = W_att[j * DIM + k];
        g_Wp[i] = __uint_as_float(f2tf32(v));
    }
}

// ---------------- kernel 2: scores + exp + warp-aggregated segment sum ----------------
// Per warp: 32 nodes (two m16 tiles share each B-fragment load).
__global__ void __launch_bounds__(256, 2) scores_kernel(
        const float* __restrict__ x,
        const void*  __restrict__ batch,
        const float* __restrict__ ctx,
        const float* __restrict__ b_att,
        int n, int nTiles) {
    extern __shared__ float sW[];   // 16384 floats = 64 KB
    for (int i = threadIdx.x; i < (JDIM * DIM) / 4; i += 256)
        ((float4*)sW)[i] = ((const float4*)g_Wp)[i];
    __syncthreads();

    const int lane = threadIdx.x & 31;
    const int wid  = threadIdx.x >> 5;
    const int gq   = lane >> 2;   // group id 0..7
    const int q    = lane & 3;    // thread-in-group
    const int warpsTotal = gridDim.x * 8;
    const int is64 = g_is64;

    for (int tile = blockIdx.x * 8 + wid; tile < nTiles; tile += warpsTotal) {
        int base = tile * 32;
        int r[4];
        const float* xp[4];
        #pragma unroll
        for (int p = 0; p < 4; p++) {
            r[p] = base + 8 * p + gq;
            int rc = (r[p] < n) ? r[p] : (n - 1);
            xp[p] = x + (size_t)rc * DIM + 4 * q;
        }

        float acc[2][8][4];
        #pragma unroll
        for (int m = 0; m < 2; m++)
            #pragma unroll
            for (int t = 0; t < 8; t++) {
                acc[m][t][0]=0.f; acc[m][t][1]=0.f; acc[m][t][2]=0.f; acc[m][t][3]=0.f;
            }

        #pragma unroll 4
        for (int ss = 0; ss < 16; ss++) {
            float4 v0 = *(const float4*)(xp[0] + 16 * ss);
            float4 v1 = *(const float4*)(xp[1] + 16 * ss);
            float4 v2 = *(const float4*)(xp[2] + 16 * ss);
            float4 v3 = *(const float4*)(xp[3] + 16 * ss);
            uint32_t a0[4] = { f2tf32(v0.x), f2tf32(v0.y), f2tf32(v0.z), f2tf32(v0.w) };
            uint32_t a1[4] = { f2tf32(v1.x), f2tf32(v1.y), f2tf32(v1.z), f2tf32(v1.w) };
            uint32_t a2[4] = { f2tf32(v2.x), f2tf32(v2.y), f2tf32(v2.z), f2tf32(v2.w) };
            uint32_t a3[4] = { f2tf32(v3.x), f2tf32(v3.y), f2tf32(v3.z), f2tf32(v3.w) };
            #pragma unroll
            for (int sub = 0; sub < 2; sub++) {
                const float2* bp = ((const float2*)sW) + ((ss * 2 + sub) * 8) * 32 + lane;
                #pragma unroll
                for (int t = 0; t < 8; t++) {
                    float2 b = bp[t * 32];
                    uint32_t bx = __float_as_uint(b.x), by = __float_as_uint(b.y);
                    mma_tf32(acc[0][t], a0[2*sub], a1[2*sub], a0[2*sub+1], a1[2*sub+1], bx, by);
                    mma_tf32(acc[1][t], a2[2*sub], a3[2*sub], a2[2*sub+1], a3[2*sub+1], bx, by);
                }
            }
        }

        // epilogue: tanh, dot with ctx, quad reduction (all quad lanes end with the sum)
        float sc[2][2];   // [m][p]: node = base + 16m + 8p + gq
        #pragma unroll
        for (int m = 0; m < 2; m++) {
            float slo = 0.f, shi = 0.f;
            #pragma unroll
            for (int t = 0; t < 8; t++) {
                int j0 = 8 * t + 2 * q;
                float c0 = ctx[j0], c1 = ctx[j0 + 1];
                float bb0 = b_att[j0], bb1 = b_att[j0 + 1];
                slo += c0 * tanh_apx(acc[m][t][0] + bb0) + c1 * tanh_apx(acc[m][t][1] + bb1);
                shi += c0 * tanh_apx(acc[m][t][2] + bb0) + c1 * tanh_apx(acc[m][t][3] + bb1);
            }
            slo += __shfl_xor_sync(0xffffffffu, slo, 1);
            slo += __shfl_xor_sync(0xffffffffu, slo, 2);
            shi += __shfl_xor_sync(0xffffffffu, shi, 1);
            shi += __shfl_xor_sync(0xffffffffu, shi, 2);
            sc[m][0] = slo; sc[m][1] = shi;
        }

        // redistribute so lane l owns node base+l  (l = 16*m + 8*p + g)
        int g_  = lane & 7;
        int src = g_ * 4;
        float v00 = __shfl_sync(0xffffffffu, sc[0][0], src);
        float v01 = __shfl_sync(0xffffffffu, sc[0][1], src);
        float v10 = __shfl_sync(0xffffffffu, sc[1][0], src);
        float v11 = __shfl_sync(0xffffffffu, sc[1][1], src);
        float score = (lane & 16) ? ((lane & 8) ? v11 : v10)
                                  : ((lane & 8) ? v01 : v00);

        int node = base + lane;
        int nodec = (node < n) ? node : (n - 1);
        float e = (node < n) ? __expf(score) : 0.f;
        if (node < n) g_expw[node] = e;            // coalesced 128B store

        int s;
        if (is64) s = (int)((const long long*)batch)[nodec];
        else      s = ((const int*)batch)[nodec];

        int s0  = __shfl_sync(0xffffffffu, s, 0);
        int s31 = __shfl_sync(0xffffffffu, s, 31);
        if (s0 == s31) {                            // whole warp in one segment (common: sorted)
            float t = e;
            #pragma unroll
            for (int o = 16; o; o >>= 1) t += __shfl_xor_sync(0xffffffffu, t, o);
            if (lane == 0) atomicAdd(&g_segsum[s0], t);
        } else if (node < n) {
            atomicAdd(&g_segsum[s], e);
        }
    }
}

// ---------------- kernel 3: CSR segment starts via binary search (batch sorted, L2-hot) ----------------
__global__ void csr_kernel(const void* __restrict__ batch, int n) {
    int s = blockIdx.x * blockDim.x + threadIdx.x;
    if (s > BMAX) return;
    int lo = 0, hi = n;
    if (g_is64) {
        const long long* b = (const long long*)batch;
        while (lo < hi) { int mid = (lo + hi) >> 1; if (b[mid] < (long long)s) lo = mid + 1; else hi = mid; }
    } else {
        const int* b = (const int*)batch;
        while (lo < hi) { int mid = (lo + hi) >> 1; if (b[mid] < s) lo = mid + 1; else hi = mid; }
    }
    g_segstart[s] = lo;
}

// ---------------- kernel 4: CSR weighted pooling (unnormalized: sum of e_i * x_i) ----------------
__global__ void __launch_bounds__(256) pool_kernel(const float* __restrict__ x) {
    __shared__ float wsh[256];
    int s    = blockIdx.x / SPLIT;
    int part = blockIdx.x % SPLIT;
    int st = g_segstart[s], en = g_segstart[s + 1];
    int len = en - st;
    int chunk = (len + SPLIT - 1) / SPLIT;
    int a  = st + part * chunk;
    int bE = a + chunk; if (bE > en) bE = en;
    if (a >= bE) return;

    const int d = threadIdx.x;
    float acc = 0.f;

    for (int base = a; base < bE; base += 256) {
        int m = bE - base; if (m > 256) m = 256;
        __syncthreads();
        if (d < m) wsh[d] = g_expw[base + d];
        __syncthreads();
        const float* xrow = x + (size_t)base * DIM + d;
        int i = 0;
        for (; i + 8 <= m; i += 8) {
            float v0 = xrow[(size_t)(i + 0) * DIM];
            float v1 = xrow[(size_t)(i + 1) * DIM];
            float v2 = xrow[(size_t)(i + 2) * DIM];
            float v3 = xrow[(size_t)(i + 3) * DIM];
            float v4 = xrow[(size_t)(i + 4) * DIM];
            float v5 = xrow[(size_t)(i + 5) * DIM];
            float v6 = xrow[(size_t)(i + 6) * DIM];
            float v7 = xrow[(size_t)(i + 7) * DIM];
            acc = fmaf(v0, wsh[i + 0], acc);
            acc = fmaf(v1, wsh[i + 1], acc);
            acc = fmaf(v2, wsh[i + 2], acc);
            acc = fmaf(v3, wsh[i + 3], acc);
            acc = fmaf(v4, wsh[i + 4], acc);
            acc = fmaf(v5, wsh[i + 5], acc);
            acc = fmaf(v6, wsh[i + 6], acc);
            acc = fmaf(v7, wsh[i + 7], acc);
        }
        for (; i < m; i++)
            acc = fmaf(xrow[(size_t)i * DIM], wsh[i], acc);
    }
    atomicAdd(&g_pooled[s * DIM + d], acc);
}

// ---------------- kernel 5: output GEMM (normalization folded in) ----------------
__global__ void __launch_bounds__(256) out_kernel(
        const float* __restrict__ W_out, const float* __restrict__ b_out,
        float* __restrict__ out, int Bn) {
    __shared__ float sp[8 * DIM];
    __shared__ float sinv[8];
    int g0 = blockIdx.x * 8;
    for (int i = threadIdx.x; i < 8 * DIM; i += 256) {
        int gg = g0 + (i >> 8);
        sp[i] = (gg < Bn) ? g_pooled[gg * DIM + (i & 255)] : 0.f;
    }
    if (threadIdx.x < 8) {
        int gg = g0 + threadIdx.x;
        float ss = (gg < Bn) ? g_segsum[gg] : 0.f;
        sinv[threadIdx.x] = (ss > 0.f) ? (1.f / ss) : 0.f;
    }
    __syncthreads();
    int d = threadIdx.x;
    float acc[8];
    #pragma unroll
    for (int g = 0; g < 8; g++) acc[g] = 0.f;
    const float4* w4 = (const float4*)(W_out + (size_t)d * DIM);
    #pragma unroll 8
    for (int k4 = 0; k4 < DIM / 4; k4++) {
        float4 w = w4[k4];
        #pragma unroll
        for (int g = 0; g < 8; g++) {
            float4 p = *(const float4*)&sp[g * DIM + 4 * k4];
            acc[g] += w.x * p.x + w.y * p.y + w.z * p.z + w.w * p.w;
        }
    }
    float bb = b_out[d];
    #pragma unroll
    for (int g = 0; g < 8; g++)
        if (g0 + g < Bn) out[(size_t)(g0 + g) * DIM + d] = acc[g] * sinv[g] + bb;
}

// ---------------- launch ----------------
extern "C" void kernel_launch(void* const* d_in, const int* in_sizes, int n_in,
                              void* d_out, int out_size) {
    const float* x     = (const float*)d_in[0];
    const void*  batch = d_in[1];
    const float* W_att = (const float*)d_in[2];
    const float* b_att = (const float*)d_in[3];
    const float* ctx   = (const float*)d_in[4];
    const float* W_out = (const float*)d_in[5];
    const float* b_out = (const float*)d_in[6];
    float* out = (float*)d_out;

    int n  = in_sizes[0] / DIM;       // 500000
    int Bn = out_size / DIM;          // 512
    int nTiles = (n + 31) / 32;

    cudaFuncSetAttribute(scores_kernel, cudaFuncAttributeMaxDynamicSharedMemorySize, 65536);

    detect_kernel<<<1, 256>>>(batch);
    init_kernel<<<(BMAX * DIM + 255) / 256, 256>>>(W_att);
    scores_kernel<<<296, 256, 65536>>>(x, batch, ctx, b_att, n, nTiles);
    csr_kernel<<<(BMAX + 256) / 256, 256>>>(batch, n);
    pool_kernel<<<BMAX * SPLIT, 256>>>(x);
    out_kernel<<<(Bn + 7) / 8, 256>>>(W_out, b_out, out, Bn);
}

// round 10
// speedup vs baseline: 1.3255x; 1.3255x over previous
#include <cuda_runtime.h>
#include <cuda_bf16.h>
#include <cstdint>

// Problem constants
#define NN      500000
#define DIM     256
#define JDIM    64
#define BMAX    512
#define SPLIT   4

// ---------------- device scratch (static, no allocation) ----------------
__device__ float    g_scores[NN];
__device__ int      g_segstart[BMAX + 1];
__device__ float    g_segsum[BMAX];
__device__ float    g_pooled[BMAX * DIM];
__device__ float    g_Wp[JDIM * DIM];   // W_att permuted into mma B-fragment order (tf32-rounded)
__device__ int      g_is64;

// ---------------- helpers ----------------
__device__ __forceinline__ uint32_t f2tf32(float f) {
    uint32_t u; asm("cvt.rna.tf32.f32 %0, %1;" : "=r"(u) : "f"(f)); return u;
}
__device__ __forceinline__ float tanh_apx(float x) {
    float y; asm("tanh.approx.f32 %0, %1;" : "=f"(y) : "f"(x)); return y;
}
__device__ __forceinline__ void mma_tf32(float (&c)[4],
        uint32_t a0, uint32_t a1, uint32_t a2, uint32_t a3,
        uint32_t b0, uint32_t b1) {
    asm volatile(
        "mma.sync.aligned.m16n8k8.row.col.f32.tf32.tf32.f32 "
        "{%0,%1,%2,%3}, {%4,%5,%6,%7}, {%8,%9}, {%0,%1,%2,%3};\n"
        : "+f"(c[0]), "+f"(c[1]), "+f"(c[2]), "+f"(c[3])
        : "r"(a0), "r"(a1), "r"(a2), "r"(a3), "r"(b0), "r"(b1));
}

// ---------------- kernel 0: detect batch dtype (int32 vs int64) ----------------
__global__ void detect_kernel(const void* batch) {
    const int* w = (const int*)batch;
    __shared__ int cnt;
    if (threadIdx.x == 0) cnt = 0;
    __syncthreads();
    int widx = 2 * 977 * (int)threadIdx.x + 1;   // odd 32-bit words, spread across array
    int z = (w[widx] == 0) ? 1 : 0;
    atomicAdd(&cnt, z);
    __syncthreads();
    if (threadIdx.x == 0) g_is64 = (cnt > 128) ? 1 : 0;
}

// ---------------- kernel 1: fused batch stream -> segment starts (batch sorted) ----------------
__global__ void boundary_kernel(const void* __restrict__ batch, int n) {
    int i = blockIdx.x * blockDim.x + threadIdx.x;
    if (i >= n) return;
    int b, prev;
    if (g_is64) {
        const long long* p = (const long long*)batch;
        b = (int)p[i];
        prev = (i == 0) ? -1 : (int)p[i - 1];
    } else {
        const int* p = (const int*)batch;
        b = p[i];
        prev = (i == 0) ? -1 : p[i - 1];
    }
    if (b != prev)                       // covers empty segments too
        for (int s = prev + 1; s <= b; s++) g_segstart[s] = i;
    if (i == n - 1)
        for (int s = b + 1; s <= BMAX; s++) g_segstart[s] = n;
}

// ---------------- kernel 2: init scratch + build permuted W (tf32-rounded) ----------------
// Wp float index = (((ss*2+sub)*8 + t)*32 + lane)*2 + c
//   j = 8*t + lane/4 ; k = 16*ss + 4*(lane%4) + 2*sub + c
__global__ void init_kernel(const float* __restrict__ W_att) {
    int i = blockIdx.x * blockDim.x + threadIdx.x;
    if (i < BMAX * DIM) g_pooled[i] = 0.f;
    if (i < BMAX) g_segsum[i] = 0.f;
    if (i < JDIM * DIM) {
        int c    = i & 1;
        int lane = (i >> 1) & 31;
        int t    = (i >> 6) & 7;
        int sub  = (i >> 9) & 1;
        int ss   = i >> 10;
        int j = 8 * t + (lane >> 2);
        int k = 16 * ss + 4 * (lane & 3) + 2 * sub + c;
        float v = W_att[j * DIM + k];
        g_Wp[i] = __uint_as_float(f2tf32(v));
    }
}

// ---------------- kernel 3: scores via tf32 tensor-core GEMM (R5-proven) ----------------
// Per warp: 32 nodes (two m16 tiles share each B-fragment load).
__global__ void __launch_bounds__(256, 2) scores_kernel(
        const float* __restrict__ x,
        const float* __restrict__ ctx,
        const float* __restrict__ b_att,
        int n, int nTiles) {
    extern __shared__ float sW[];   // 16384 floats = 64 KB
    for (int i = threadIdx.x; i < (JDIM * DIM) / 4; i += 256)
        ((float4*)sW)[i] = ((const float4*)g_Wp)[i];
    __syncthreads();

    const int lane = threadIdx.x & 31;
    const int wid  = threadIdx.x >> 5;
    const int gq   = lane >> 2;   // group id 0..7
    const int q    = lane & 3;    // thread-in-group
    const int warpsTotal = gridDim.x * 8;

    for (int tile = blockIdx.x * 8 + wid; tile < nTiles; tile += warpsTotal) {
        int base = tile * 32;
        int r[4];
        const float* xp[4];
        #pragma unroll
        for (int p = 0; p < 4; p++) {
            r[p] = base + 8 * p + gq;
            int rc = (r[p] < n) ? r[p] : (n - 1);
            xp[p] = x + (size_t)rc * DIM + 4 * q;
        }

        float acc[2][8][4];
        #pragma unroll
        for (int m = 0; m < 2; m++)
            #pragma unroll
            for (int t = 0; t < 8; t++) {
                acc[m][t][0]=0.f; acc[m][t][1]=0.f; acc[m][t][2]=0.f; acc[m][t][3]=0.f;
            }

        #pragma unroll 4
        for (int ss = 0; ss < 16; ss++) {
            float4 v0 = *(const float4*)(xp[0] + 16 * ss);
            float4 v1 = *(const float4*)(xp[1] + 16 * ss);
            float4 v2 = *(const float4*)(xp[2] + 16 * ss);
            float4 v3 = *(const float4*)(xp[3] + 16 * ss);
            uint32_t a0[4] = { f2tf32(v0.x), f2tf32(v0.y), f2tf32(v0.z), f2tf32(v0.w) };
            uint32_t a1[4] = { f2tf32(v1.x), f2tf32(v1.y), f2tf32(v1.z), f2tf32(v1.w) };
            uint32_t a2[4] = { f2tf32(v2.x), f2tf32(v2.y), f2tf32(v2.z), f2tf32(v2.w) };
            uint32_t a3[4] = { f2tf32(v3.x), f2tf32(v3.y), f2tf32(v3.z), f2tf32(v3.w) };
            #pragma unroll
            for (int sub = 0; sub < 2; sub++) {
                const float2* bp = ((const float2*)sW) + ((ss * 2 + sub) * 8) * 32 + lane;
                #pragma unroll
                for (int t = 0; t < 8; t++) {
                    float2 b = bp[t * 32];
                    uint32_t bx = __float_as_uint(b.x), by = __float_as_uint(b.y);
                    mma_tf32(acc[0][t], a0[2*sub], a1[2*sub], a0[2*sub+1], a1[2*sub+1], bx, by);
                    mma_tf32(acc[1][t], a2[2*sub], a3[2*sub], a2[2*sub+1], a3[2*sub+1], bx, by);
                }
            }
        }

        // epilogue: tanh, dot with ctx, quad reduction (per m16 tile: nodes r[2m], r[2m+1])
        #pragma unroll
        for (int m = 0; m < 2; m++) {
            float slo = 0.f, shi = 0.f;
            #pragma unroll
            for (int t = 0; t < 8; t++) {
                int j0 = 8 * t + 2 * q;
                float c0 = ctx[j0], c1 = ctx[j0 + 1];
                float bb0 = b_att[j0], bb1 = b_att[j0 + 1];
                slo += c0 * tanh_apx(acc[m][t][0] + bb0) + c1 * tanh_apx(acc[m][t][1] + bb1);
                shi += c0 * tanh_apx(acc[m][t][2] + bb0) + c1 * tanh_apx(acc[m][t][3] + bb1);
            }
            slo += __shfl_xor_sync(0xffffffffu, slo, 1);
            slo += __shfl_xor_sync(0xffffffffu, slo, 2);
            shi += __shfl_xor_sync(0xffffffffu, shi, 1);
            shi += __shfl_xor_sync(0xffffffffu, shi, 2);
            if (q == 0) {
                if (r[2*m]   < n) g_scores[r[2*m]]   = slo;
                if (r[2*m+1] < n) g_scores[r[2*m+1]] = shi;
            }
        }
    }
}

// ---------------- kernel 4: CSR pooling with fused exp + segment-sum ----------------
// grid = BMAX*SPLIT blocks; block (s, part) covers a slice of segment s's nodes.
// Stages w = exp(score) into smem (max-free softmax: |score| <= sum|ctx| ~ 5, exp safe),
// accumulates unnormalized pooled = sum(e_i * x_i) and this block's partial sum(e_i).
__global__ void __launch_bounds__(256) pool_kernel(const float* __restrict__ x) {
    __shared__ float wsh[256];
    __shared__ float wred[8];
    int s    = blockIdx.x / SPLIT;
    int part = blockIdx.x % SPLIT;
    int st = g_segstart[s], en = g_segstart[s + 1];
    int len = en - st;
    int chunk = (len + SPLIT - 1) / SPLIT;
    int a  = st + part * chunk;
    int bE = a + chunk; if (bE > en) bE = en;
    if (a >= bE) return;

    const int d = threadIdx.x;
    float acc  = 0.f;
    float wacc = 0.f;   // this thread's staged exp values (each node staged exactly once)

    for (int base = a; base < bE; base += 256) {
        int m = bE - base; if (m > 256) m = 256;
        __syncthreads();
        if (d < m) {
            float e = __expf(g_scores[base + d]);
            wsh[d] = e;
            wacc += e;
        }
        __syncthreads();
        const float* xrow = x + (size_t)base * DIM + d;
        int i = 0;
        for (; i + 8 <= m; i += 8) {
            float v0 = xrow[(size_t)(i + 0) * DIM];
            float v1 = xrow[(size_t)(i + 1) * DIM];
            float v2 = xrow[(size_t)(i + 2) * DIM];
            float v3 = xrow[(size_t)(i + 3) * DIM];
            float v4 = xrow[(size_t)(i + 4) * DIM];
            float v5 = xrow[(size_t)(i + 5) * DIM];
            float v6 = xrow[(size_t)(i + 6) * DIM];
            float v7 = xrow[(size_t)(i + 7) * DIM];
            acc = fmaf(v0, wsh[i + 0], acc);
            acc = fmaf(v1, wsh[i + 1], acc);
            acc = fmaf(v2, wsh[i + 2], acc);
            acc = fmaf(v3, wsh[i + 3], acc);
            acc = fmaf(v4, wsh[i + 4], acc);
            acc = fmaf(v5, wsh[i + 5], acc);
            acc = fmaf(v6, wsh[i + 6], acc);
            acc = fmaf(v7, wsh[i + 7], acc);
        }
        for (; i < m; i++)
            acc = fmaf(xrow[(size_t)i * DIM], wsh[i], acc);
    }
    atomicAdd(&g_pooled[s * DIM + d], acc);

    // block-reduce wacc -> one atomicAdd to g_segsum[s]
    #pragma unroll
    for (int o = 16; o; o >>= 1) wacc += __shfl_xor_sync(0xffffffffu, wacc, o);
    if ((d & 31) == 0) wred[d >> 5] = wacc;
    __syncthreads();
    if (d == 0) {
        float t = wred[0] + wred[1] + wred[2] + wred[3]
                + wred[4] + wred[5] + wred[6] + wred[7];
        atomicAdd(&g_segsum[s], t);
    }
}

// ---------------- kernel 5: output GEMM (normalization folded in) ----------------
__global__ void __launch_bounds__(256) out_kernel(
        const float* __restrict__ W_out, const float* __restrict__ b_out,
        float* __restrict__ out, int Bn) {
    __shared__ float sp[8 * DIM];
    __shared__ float sinv[8];
    int g0 = blockIdx.x * 8;
    for (int i = threadIdx.x; i < 8 * DIM; i += 256) {
        int gg = g0 + (i >> 8);
        sp[i] = (gg < Bn) ? g_pooled[gg * DIM + (i & 255)] : 0.f;
    }
    if (threadIdx.x < 8) {
        int gg = g0 + threadIdx.x;
        float ss = (gg < Bn) ? g_segsum[gg] : 0.f;
        sinv[threadIdx.x] = (ss > 0.f) ? (1.f / ss) : 0.f;
    }
    __syncthreads();
    int d = threadIdx.x;
    float acc[8];
    #pragma unroll
    for (int g = 0; g < 8; g++) acc[g] = 0.f;
    const float4* w4 = (const float4*)(W_out + (size_t)d * DIM);
    #pragma unroll 8
    for (int k4 = 0; k4 < DIM / 4; k4++) {
        float4 w = w4[k4];
        #pragma unroll
        for (int g = 0; g < 8; g++) {
            float4 p = *(const float4*)&sp[g * DIM + 4 * k4];
            acc[g] += w.x * p.x + w.y * p.y + w.z * p.z + w.w * p.w;
        }
    }
    float bb = b_out[d];
    #pragma unroll
    for (int g = 0; g < 8; g++)
        if (g0 + g < Bn) out[(size_t)(g0 + g) * DIM + d] = acc[g] * sinv[g] + bb;
}

// ---------------- launch ----------------
extern "C" void kernel_launch(void* const* d_in, const int* in_sizes, int n_in,
                              void* d_out, int out_size) {
    const float* x     = (const float*)d_in[0];
    const void*  batch = d_in[1];
    const float* W_att = (const float*)d_in[2];
    const float* b_att = (const float*)d_in[3];
    const float* ctx   = (const float*)d_in[4];
    const float* W_out = (const float*)d_in[5];
    const float* b_out = (const float*)d_in[6];
    float* out = (float*)d_out;

    int n  = in_sizes[0] / DIM;       // 500000
    int Bn = out_size / DIM;          // 512
    int nTiles = (n + 31) / 32;

    cudaFuncSetAttribute(scores_kernel, cudaFuncAttributeMaxDynamicSharedMemorySize, 65536);

    detect_kernel<<<1, 256>>>(batch);
    boundary_kernel<<<(n + 255) / 256, 256>>>(batch, n);
    init_kernel<<<(BMAX * DIM + 255) / 256, 256>>>(W_att);
    scores_kernel<<<296, 256, 65536>>>(x, ctx, b_att, n, nTiles);
    pool_kernel<<<BMAX * SPLIT, 256>>>(x);
    out_kernel<<<(Bn + 7) / 8, 256>>>(W_out, b_out, out, Bn);
}

// round 14
// speedup vs baseline: 1.4487x; 1.0929x over previous
#include <cuda_runtime.h>
#include <cuda_bf16.h>
#include <cstdint>

// Problem constants
#define NN      500000
#define DIM     256
#define JDIM    64
#define BMAX    512
#define SPLIT   4

// ---------------- device scratch (static, no allocation) ----------------
__device__ float    g_scores[NN];
__device__ int      g_segstart[BMAX + 1];
__device__ float    g_segsum[BMAX];
__device__ float    g_pooled[BMAX * DIM];
__device__ float    g_Wp[JDIM * DIM];   // W_att permuted into mma B-fragment order (tf32-rounded)
__device__ int      g_is64;

// ---------------- helpers ----------------
__device__ __forceinline__ uint32_t f2tf32(float f) {
    uint32_t u; asm("cvt.rna.tf32.f32 %0, %1;" : "=r"(u) : "f"(f)); return u;
}
__device__ __forceinline__ float tanh_apx(float x) {
    float y; asm("tanh.approx.f32 %0, %1;" : "=f"(y) : "f"(x)); return y;
}
__device__ __forceinline__ void mma_tf32(float (&c)[4],
        uint32_t a0, uint32_t a1, uint32_t a2, uint32_t a3,
        uint32_t b0, uint32_t b1) {
    asm volatile(
        "mma.sync.aligned.m16n8k8.row.col.f32.tf32.tf32.f32 "
        "{%0,%1,%2,%3}, {%4,%5,%6,%7}, {%8,%9}, {%0,%1,%2,%3};\n"
        : "+f"(c[0]), "+f"(c[1]), "+f"(c[2]), "+f"(c[3])
        : "r"(a0), "r"(a1), "r"(a2), "r"(a3), "r"(b0), "r"(b1));
}

// ---------------- kernel 0: detect batch dtype (int32 vs int64) ----------------
__global__ void detect_kernel(const void* batch) {
    const int* w = (const int*)batch;
    __shared__ int cnt;
    if (threadIdx.x == 0) cnt = 0;
    __syncthreads();
    int widx = 2 * 977 * (int)threadIdx.x + 1;   // odd 32-bit words, spread across array
    int z = (w[widx] == 0) ? 1 : 0;
    atomicAdd(&cnt, z);
    __syncthreads();
    if (threadIdx.x == 0) g_is64 = (cnt > 128) ? 1 : 0;
}

// ---------------- kernel 1: fused batch stream -> segment starts (batch sorted) ----------------
__global__ void boundary_kernel(const void* __restrict__ batch, int n) {
    int i = blockIdx.x * blockDim.x + threadIdx.x;
    if (i >= n) return;
    int b, prev;
    if (g_is64) {
        const long long* p = (const long long*)batch;
        b = (int)p[i];
        prev = (i == 0) ? -1 : (int)p[i - 1];
    } else {
        const int* p = (const int*)batch;
        b = p[i];
        prev = (i == 0) ? -1 : p[i - 1];
    }
    if (b != prev)                       // covers empty segments too
        for (int s = prev + 1; s <= b; s++) g_segstart[s] = i;
    if (i == n - 1)
        for (int s = b + 1; s <= BMAX; s++) g_segstart[s] = n;
}

// ---------------- kernel 2: init scratch + build permuted W (tf32-rounded) ----------------
// Wp float index = (((ss*2+sub)*8 + t)*32 + lane)*2 + c
//   j = 8*t + lane/4 ; k = 16*ss + 4*(lane%4) + 2*sub + c
__global__ void init_kernel(const float* __restrict__ W_att) {
    int i = blockIdx.x * blockDim.x + threadIdx.x;
    if (i < BMAX * DIM) g_pooled[i] = 0.f;
    if (i < BMAX) g_segsum[i] = 0.f;
    if (i < JDIM * DIM) {
        int c    = i & 1;
        int lane = (i >> 1) & 31;
        int t    = (i >> 6) & 7;
        int sub  = (i >> 9) & 1;
        int ss   = i >> 10;
        int j = 8 * t + (lane >> 2);
        int k = 16 * ss + 4 * (lane & 3) + 2 * sub + c;
        float v = W_att[j * DIM + k];
        g_Wp[i] = __uint_as_float(f2tf32(v));
    }
}

// ---------------- kernel 3: scores via tf32 tensor-core GEMM ----------------
// R2-proven config: 16 nodes per warp, 78 regs, occ ~35%, measured 113us.
__global__ void __launch_bounds__(256) scores_kernel(
        const float* __restrict__ x,
        const float* __restrict__ ctx,
        const float* __restrict__ b_att,
        int n, int nTiles) {
    extern __shared__ float sW[];   // 16384 floats = 64 KB
    for (int i = threadIdx.x; i < (JDIM * DIM) / 4; i += 256)
        ((float4*)sW)[i] = ((const float4*)g_Wp)[i];
    __syncthreads();

    const int lane = threadIdx.x & 31;
    const int wid  = threadIdx.x >> 5;
    const int gq   = lane >> 2;   // group id 0..7
    const int q    = lane & 3;    // thread-in-group
    const int warpsTotal = gridDim.x * 8;

    for (int tile = blockIdx.x * 8 + wid; tile < nTiles; tile += warpsTotal) {
        int r0 = tile * 16 + gq;
        int r1 = r0 + 8;
        int r0c = (r0 < n) ? r0 : (n - 1);
        int r1c = (r1 < n) ? r1 : (n - 1);
        const float* xr0 = x + (size_t)r0c * DIM + 4 * q;
        const float* xr1 = x + (size_t)r1c * DIM + 4 * q;

        float acc[8][4];
        #pragma unroll
        for (int t = 0; t < 8; t++) { acc[t][0]=0.f; acc[t][1]=0.f; acc[t][2]=0.f; acc[t][3]=0.f; }

        #pragma unroll 4
        for (int ss = 0; ss < 16; ss++) {
            float4 xlo = *(const float4*)(xr0 + 16 * ss);
            float4 xhi = *(const float4*)(xr1 + 16 * ss);
            uint32_t al[4] = { f2tf32(xlo.x), f2tf32(xlo.y), f2tf32(xlo.z), f2tf32(xlo.w) };
            uint32_t ah[4] = { f2tf32(xhi.x), f2tf32(xhi.y), f2tf32(xhi.z), f2tf32(xhi.w) };
            #pragma unroll
            for (int sub = 0; sub < 2; sub++) {
                const float2* bp = ((const float2*)sW) + ((ss * 2 + sub) * 8) * 32 + lane;
                #pragma unroll
                for (int t = 0; t < 8; t++) {
                    float2 b = bp[t * 32];
                    mma_tf32(acc[t], al[2*sub], ah[2*sub], al[2*sub+1], ah[2*sub+1],
                             __float_as_uint(b.x), __float_as_uint(b.y));
                }
            }
        }

        // epilogue: tanh, dot with ctx, quad reduction
        float slo = 0.f, shi = 0.f;
        #pragma unroll
        for (int t = 0; t < 8; t++) {
            int j0 = 8 * t + 2 * q;
            float c0 = ctx[j0], c1 = ctx[j0 + 1];
            float bb0 = b_att[j0], bb1 = b_att[j0 + 1];
            slo += c0 * tanh_apx(acc[t][0] + bb0) + c1 * tanh_apx(acc[t][1] + bb1);
            shi += c0 * tanh_apx(acc[t][2] + bb0) + c1 * tanh_apx(acc[t][3] + bb1);
        }
        slo += __shfl_xor_sync(0xffffffffu, slo, 1);
        slo += __shfl_xor_sync(0xffffffffu, slo, 2);
        shi += __shfl_xor_sync(0xffffffffu, shi, 1);
        shi += __shfl_xor_sync(0xffffffffu, shi, 2);
        if (q == 0) {
            if (r0 < n) g_scores[r0] = slo;
            if (r1 < n) g_scores[r1] = shi;
        }
    }
}

// ---------------- kernel 4: CSR pooling with fused exp + segment-sum ----------------
// grid = BMAX*SPLIT blocks; block (s, part) covers a slice of segment s's nodes.
// Stages w = exp(score) into smem (max-free softmax: |score| <= sum|ctx| ~ 5, exp safe),
// accumulates unnormalized pooled = sum(e_i * x_i) and this block's partial sum(e_i).
__global__ void __launch_bounds__(256) pool_kernel(const float* __restrict__ x) {
    __shared__ float wsh[256];
    __shared__ float wred[8];
    int s    = blockIdx.x / SPLIT;
    int part = blockIdx.x % SPLIT;
    int st = g_segstart[s], en = g_segstart[s + 1];
    int len = en - st;
    int chunk = (len + SPLIT - 1) / SPLIT;
    int a  = st + part * chunk;
    int bE = a + chunk; if (bE > en) bE = en;
    if (a >= bE) return;

    const int d = threadIdx.x;
    float acc  = 0.f;
    float wacc = 0.f;   // this thread's staged exp values (each node staged exactly once)

    for (int base = a; base < bE; base += 256) {
        int m = bE - base; if (m > 256) m = 256;
        __syncthreads();
        if (d < m) {
            float e = __expf(g_scores[base + d]);
            wsh[d] = e;
            wacc += e;
        }
        __syncthreads();
        const float* xrow = x + (size_t)base * DIM + d;
        int i = 0;
        for (; i + 8 <= m; i += 8) {
            float v0 = xrow[(size_t)(i + 0) * DIM];
            float v1 = xrow[(size_t)(i + 1) * DIM];
            float v2 = xrow[(size_t)(i + 2) * DIM];
            float v3 = xrow[(size_t)(i + 3) * DIM];
            float v4 = xrow[(size_t)(i + 4) * DIM];
            float v5 = xrow[(size_t)(i + 5) * DIM];
            float v6 = xrow[(size_t)(i + 6) * DIM];
            float v7 = xrow[(size_t)(i + 7) * DIM];
            acc = fmaf(v0, wsh[i + 0], acc);
            acc = fmaf(v1, wsh[i + 1], acc);
            acc = fmaf(v2, wsh[i + 2], acc);
            acc = fmaf(v3, wsh[i + 3], acc);
            acc = fmaf(v4, wsh[i + 4], acc);
            acc = fmaf(v5, wsh[i + 5], acc);
            acc = fmaf(v6, wsh[i + 6], acc);
            acc = fmaf(v7, wsh[i + 7], acc);
        }
        for (; i < m; i++)
            acc = fmaf(xrow[(size_t)i * DIM], wsh[i], acc);
    }
    atomicAdd(&g_pooled[s * DIM + d], acc);

    // block-reduce wacc -> one atomicAdd to g_segsum[s]
    #pragma unroll
    for (int o = 16; o; o >>= 1) wacc += __shfl_xor_sync(0xffffffffu, wacc, o);
    if ((d & 31) == 0) wred[d >> 5] = wacc;
    __syncthreads();
    if (d == 0) {
        float t = wred[0] + wred[1] + wred[2] + wred[3]
                + wred[4] + wred[5] + wred[6] + wred[7];
        atomicAdd(&g_segsum[s], t);
    }
}

// ---------------- kernel 5: output GEMM (normalization folded in) ----------------
__global__ void __launch_bounds__(256) out_kernel(
        const float* __restrict__ W_out, const float* __restrict__ b_out,
        float* __restrict__ out, int Bn) {
    __shared__ float sp[8 * DIM];
    __shared__ float sinv[8];
    int g0 = blockIdx.x * 8;
    for (int i = threadIdx.x; i < 8 * DIM; i += 256) {
        int gg = g0 + (i >> 8);
        sp[i] = (gg < Bn) ? g_pooled[gg * DIM + (i & 255)] : 0.f;
    }
    if (threadIdx.x < 8) {
        int gg = g0 + threadIdx.x;
        float ss = (gg < Bn) ? g_segsum[gg] : 0.f;
        sinv[threadIdx.x] = (ss > 0.f) ? (1.f / ss) : 0.f;
    }
    __syncthreads();
    int d = threadIdx.x;
    float acc[8];
    #pragma unroll
    for (int g = 0; g < 8; g++) acc[g] = 0.f;
    const float4* w4 = (const float4*)(W_out + (size_t)d * DIM);
    #pragma unroll 8
    for (int k4 = 0; k4 < DIM / 4; k4++) {
        float4 w = w4[k4];
        #pragma unroll
        for (int g = 0; g < 8; g++) {
            float4 p = *(const float4*)&sp[g * DIM + 4 * k4];
            acc[g] += w.x * p.x + w.y * p.y + w.z * p.z + w.w * p.w;
        }
    }
    float bb = b_out[d];
    #pragma unroll
    for (int g = 0; g < 8; g++)
        if (g0 + g < Bn) out[(size_t)(g0 + g) * DIM + d] = acc[g] * sinv[g] + bb;
}

// ---------------- launch ----------------
extern "C" void kernel_launch(void* const* d_in, const int* in_sizes, int n_in,
                              void* d_out, int out_size) {
    const float* x     = (const float*)d_in[0];
    const void*  batch = d_in[1];
    const float* W_att = (const float*)d_in[2];
    const float* b_att = (const float*)d_in[3];
    const float* ctx   = (const float*)d_in[4];
    const float* W_out = (const float*)d_in[5];
    const float* b_out = (const float*)d_in[6];
    float* out = (float*)d_out;

    int n  = in_sizes[0] / DIM;       // 500000
    int Bn = out_size / DIM;          // 512
    int nTiles = (n + 15) / 16;

    cudaFuncSetAttribute(scores_kernel, cudaFuncAttributeMaxDynamicSharedMemorySize, 65536);

    detect_kernel<<<1, 256>>>(batch);
    boundary_kernel<<<(n + 255) / 256, 256>>>(batch, n);
    init_kernel<<<(BMAX * DIM + 255) / 256, 256>>>(W_att);
    scores_kernel<<<444, 256, 65536>>>(x, ctx, b_att, n, nTiles);
    pool_kernel<<<BMAX * SPLIT, 256>>>(x);
    out_kernel<<<(Bn + 7) / 8, 256>>>(W_out, b_out, out, Bn);
}